// round 5
// baseline (speedup 1.0000x reference)
#include <cuda_runtime.h>
#include <cstdint>

// ============================================================================
// y = ifft2(fft2(x) * sqrt_lambda), ortho. x: (16,768,64,64) f32.
// Pack 2 images as one complex field (filter real & symmetric => exact).
// One CTA (64 thr) per pair; each thread owns a full 64-pt line in registers.
// TMA bulk copies gmem<->smem; all SM-side memory ops are conflict-free smem.
// Single 32KB smem buffer reused: dense (TMA) and rotated (transposes).
// ============================================================================

#define NPIX 4096
#define NBLK 6144           // 12288 images / 2
#define TILE_BYTES 16384

__device__ float  g_perm[NPIX];   // filter, permuted: g_perm[r*64 + q] = f[r][swap(q)]
__device__ float2 g_tw[64];       // W64^{b*c} at [b*8+c]

__device__ __forceinline__ float2 cadd(float2 a, float2 b) { return make_float2(a.x + b.x, a.y + b.y); }
__device__ __forceinline__ float2 csub(float2 a, float2 b) { return make_float2(a.x - b.x, a.y - b.y); }
__device__ __forceinline__ float2 cmul(float2 a, float2 b) {
    return make_float2(fmaf(a.x, b.x, -a.y * b.y), fmaf(a.x, b.y, a.y * b.x));
}
__device__ __forceinline__ float2 cmulc(float2 a, float2 b) {  // a * conj(b)
    return make_float2(fmaf(a.x, b.x, a.y * b.y), fmaf(a.y, b.x, -a.x * b.y));
}

template <bool INV>
__device__ __forceinline__ float2 mul_i(float2 a) {
    return INV ? make_float2(-a.y, a.x) : make_float2(a.y, -a.x);
}

template <bool INV>
__device__ __forceinline__ void fft8(float2* a) {
    const float C = 0.70710678118654752440f;
    float2 e0 = a[0], e1 = a[2], e2 = a[4], e3 = a[6];
    float2 o0 = a[1], o1 = a[3], o2 = a[5], o3 = a[7];
    float2 t0 = cadd(e0, e2), t1 = csub(e0, e2);
    float2 t2 = cadd(e1, e3), t3 = mul_i<INV>(csub(e1, e3));
    float2 E0 = cadd(t0, t2), E2 = csub(t0, t2);
    float2 E1 = cadd(t1, t3), E3 = csub(t1, t3);
    t0 = cadd(o0, o2); t1 = csub(o0, o2);
    t2 = cadd(o1, o3); t3 = mul_i<INV>(csub(o1, o3));
    float2 O0 = cadd(t0, t2), O2 = csub(t0, t2);
    float2 O1 = cadd(t1, t3), O3 = csub(t1, t3);
    if (!INV) {
        O1 = make_float2(C * (O1.x + O1.y), C * (O1.y - O1.x));
        O2 = make_float2(O2.y, -O2.x);
        O3 = make_float2(C * (O3.y - O3.x), C * (-O3.x - O3.y));
    } else {
        O1 = make_float2(C * (O1.x - O1.y), C * (O1.x + O1.y));
        O2 = make_float2(-O2.y, O2.x);
        O3 = make_float2(C * (-O3.x - O3.y), C * (O3.x - O3.y));
    }
    a[0] = cadd(E0, O0); a[4] = csub(E0, O0);
    a[1] = cadd(E1, O1); a[5] = csub(E1, O1);
    a[2] = cadd(E2, O2); a[6] = csub(E2, O2);
    a[3] = cadd(E3, O3); a[7] = csub(E3, O3);
}

// 64-pt FFT, natural input. Output digit-swapped: freq (c+8d) at slot (8c+d).
template <bool INV>
__device__ __forceinline__ void fft64_nat(float2* v, const float2* Tw) {
    #pragma unroll
    for (int b = 0; b < 8; b++) {
        float2 a[8];
        #pragma unroll
        for (int j = 0; j < 8; j++) a[j] = v[b + 8 * j];
        fft8<INV>(a);
        #pragma unroll
        for (int j = 0; j < 8; j++) v[b + 8 * j] = a[j];
    }
    #pragma unroll
    for (int b = 1; b < 8; b++)
        #pragma unroll
        for (int c = 1; c < 8; c++) {
            float2 t = Tw[b * 8 + c];
            v[8 * c + b] = INV ? cmulc(v[8 * c + b], t) : cmul(v[8 * c + b], t);
        }
    #pragma unroll
    for (int c = 0; c < 8; c++) fft8<INV>(v + 8 * c);
}

// 64-pt FFT, digit-swapped input, natural output.
template <bool INV>
__device__ __forceinline__ void fft64_swapin(float2* v, const float2* Tw) {
    #pragma unroll
    for (int c = 0; c < 8; c++) fft8<INV>(v + 8 * c);
    #pragma unroll
    for (int c = 1; c < 8; c++)
        #pragma unroll
        for (int e = 1; e < 8; e++) {
            float2 t = Tw[c * 8 + e];
            v[8 * c + e] = INV ? cmulc(v[8 * c + e], t) : cmul(v[8 * c + e], t);
        }
    #pragma unroll
    for (int e = 0; e < 8; e++) {
        float2 a[8];
        #pragma unroll
        for (int cc = 0; cc < 8; cc++) a[cc] = v[8 * cc + e];
        fft8<INV>(a);
        #pragma unroll
        for (int f = 0; f < 8; f++) v[e + 8 * f] = a[f];
    }
}

// ============================================================================
// Filter + twiddle build (tiny, one block).
// ============================================================================
__global__ void build_filter_kernel(const float* __restrict__ g1p,
                                    const float* __restrict__ raw_deltas,
                                    const int* __restrict__ bin_idx) {
    __shared__ float gbin[16];
    __shared__ float red[256];
    int tid = threadIdx.x;

    if (tid < 64) {
        int b = tid >> 3, c = tid & 7;
        float sv, cv;
        sincospif(-(float)(b * c) * (1.0f / 32.0f), &sv, &cv);
        g_tw[tid] = make_float2(cv, sv);
    }
    if (tid == 0) {
        float acc = g1p[0];
        gbin[0] = acc;
        #pragma unroll
        for (int i = 0; i < 15; i++) {
            float v = raw_deltas[i];
            float sp = (v > 20.0f) ? v : log1pf(expf(v));
            acc += sp;
            gbin[i + 1] = acc;
        }
    }
    __syncthreads();

    float ell[16];
    float s = 0.0f;
    #pragma unroll
    for (int i = 0; i < 16; i++) {
        int p = tid + 256 * i;
        ell[i] = gbin[bin_idx[p]];
        s += ell[i];
    }
    red[tid] = s;
    __syncthreads();
    for (int off = 128; off > 0; off >>= 1) {
        if (tid < off) red[tid] += red[tid + off];
        __syncthreads();
    }
    float m1 = red[0] * (1.0f / 4096.0f);
    __syncthreads();

    float s2 = 0.0f;
    #pragma unroll
    for (int i = 0; i < 16; i++) {
        float e = ell[i] - m1;
        e = fminf(3.0f, fmaxf(-3.0f, e));
        ell[i] = e;
        s2 += e;
    }
    red[tid] = s2;
    __syncthreads();
    for (int off = 128; off > 0; off >>= 1) {
        if (tid < off) red[tid] += red[tid + off];
        __syncthreads();
    }
    float m2 = red[0] * (1.0f / 4096.0f);

    #pragma unroll
    for (int i = 0; i < 16; i++) {
        int p = tid + 256 * i;              // p = r*64 + j
        float val = expf(0.5f * (ell[i] - m2)) * (1.0f / 4096.0f);
        int j = p & 63;
        int q = ((j & 7) << 3) | (j >> 3);  // swap(j)
        g_perm[(p & ~63) | q] = val;
    }
}

// ============================================================================
// Main kernel.
// ============================================================================
__global__ void __launch_bounds__(64, 6)
spectral_kernel(const float* __restrict__ x, float* __restrict__ y) {
    __shared__ __align__(16) float SA[NPIX];   // 16KB: image A / re plane
    __shared__ __align__(16) float SB[NPIX];   // 16KB: image B / im plane
    __shared__ float2 Tw[64];
    __shared__ __align__(8) unsigned long long mbar;

    const int c = threadIdx.x;
    const size_t base = (size_t)blockIdx.x * (2 * NPIX);

    uint32_t sa_u32, sb_u32, mb_u32;
    {
        uint64_t t;
        asm("cvta.to.shared.u64 %0, %1;" : "=l"(t) : "l"((void*)SA)); sa_u32 = (uint32_t)t;
        asm("cvta.to.shared.u64 %0, %1;" : "=l"(t) : "l"((void*)SB)); sb_u32 = (uint32_t)t;
        asm("cvta.to.shared.u64 %0, %1;" : "=l"(t) : "l"((void*)&mbar)); mb_u32 = (uint32_t)t;
    }

    if (c == 0)
        asm volatile("mbarrier.init.shared.b64 [%0], 1;" :: "r"(mb_u32) : "memory");
    Tw[c] = g_tw[c];
    __syncthreads();

    if (c == 0) {
        asm volatile("mbarrier.arrive.expect_tx.shared.b64 _, [%0], %1;"
                     :: "r"(mb_u32), "r"(2 * TILE_BYTES) : "memory");
        asm volatile("cp.async.bulk.shared::cluster.global.mbarrier::complete_tx::bytes [%0], [%1], %2, [%3];"
                     :: "r"(sa_u32), "l"(x + base), "r"(TILE_BYTES), "r"(mb_u32) : "memory");
        asm volatile("cp.async.bulk.shared::cluster.global.mbarrier::complete_tx::bytes [%0], [%1], %2, [%3];"
                     :: "r"(sb_u32), "l"(x + base + NPIX), "r"(TILE_BYTES), "r"(mb_u32) : "memory");
    }
    {   // wait parity 0 (acquire)
        uint32_t done;
        asm volatile("{\n\t.reg .pred p;\n\t"
                     "mbarrier.try_wait.parity.acquire.cta.shared::cta.b64 p, [%1], 0;\n\t"
                     "selp.b32 %0, 1, 0, p;\n\t}"
                     : "=r"(done) : "r"(mb_u32) : "memory");
        while (!done) {
            asm volatile("{\n\t.reg .pred p;\n\t"
                         "mbarrier.try_wait.parity.acquire.cta.shared::cta.b64 p, [%1], 0;\n\t"
                         "selp.b32 %0, 1, 0, p;\n\t}"
                         : "=r"(done) : "r"(mb_u32) : "memory");
        }
    }

    float2 v[64];

    // ---- Phase 1: column c from dense tiles (conflict-free), fwd col FFT
    #pragma unroll
    for (int i = 0; i < 64; i++) {
        v[i].x = SA[i * 64 + c];
        v[i].y = SB[i * 64 + c];
    }
    fft64_nat<false>(v, Tw);
    __syncthreads();

    // ---- T1: store freq-row-major with rotation swizzle (conflict-free)
    #pragma unroll
    for (int m = 0; m < 64; m++) {
        int s = ((m & 7) << 3) | (m >> 3);          // slot holding freq m
        int a = m * 64 + ((c + m) & 63);
        SA[a] = v[s].x;
        SB[a] = v[s].y;
    }
    __syncthreads();

    // ---- Phase 2: freq-row r = c; fwd row FFT + filter + inv row FFT
    const int r = c;
    #pragma unroll
    for (int j = 0; j < 64; j++) {
        int a = r * 64 + ((j + r) & 63);
        v[j].x = SA[a];
        v[j].y = SB[a];
    }
    fft64_nat<false>(v, Tw);
    {
        const float4* F = (const float4*)g_perm;
        #pragma unroll
        for (int k = 0; k < 16; k++) {
            float4 f = __ldg(&F[r * 16 + k]);
            v[4 * k + 0].x *= f.x; v[4 * k + 0].y *= f.x;
            v[4 * k + 1].x *= f.y; v[4 * k + 1].y *= f.y;
            v[4 * k + 2].x *= f.z; v[4 * k + 2].y *= f.z;
            v[4 * k + 3].x *= f.w; v[4 * k + 3].y *= f.w;
        }
    }
    fft64_swapin<true>(v, Tw);
    __syncthreads();

    // ---- T2: store row r back (natural j order, rotated)
    #pragma unroll
    for (int j = 0; j < 64; j++) {
        int a = r * 64 + ((j + r) & 63);
        SA[a] = v[j].x;
        SB[a] = v[j].y;
    }
    __syncthreads();

    // ---- Phase 3: column c (rotated read), inv col FFT
    #pragma unroll
    for (int m = 0; m < 64; m++) {
        int a = m * 64 + ((c + m) & 63);
        v[m].x = SA[a];
        v[m].y = SB[a];
    }
    fft64_nat<true>(v, Tw);
    __syncthreads();

    // ---- Final: dense store spatial row i from slot swap(i)
    #pragma unroll
    for (int i = 0; i < 64; i++) {
        int s = ((i & 7) << 3) | (i >> 3);
        SA[i * 64 + c] = v[s].x;
        SB[i * 64 + c] = v[s].y;
    }
    __syncthreads();

    if (c == 0) {
        asm volatile("fence.proxy.async.shared::cta;" ::: "memory");
        asm volatile("cp.async.bulk.global.shared::cta.bulk_group [%0], [%1], %2;"
                     :: "l"(y + base), "r"(sa_u32), "r"(TILE_BYTES) : "memory");
        asm volatile("cp.async.bulk.global.shared::cta.bulk_group [%0], [%1], %2;"
                     :: "l"(y + base + NPIX), "r"(sb_u32), "r"(TILE_BYTES) : "memory");
        asm volatile("cp.async.bulk.commit_group;" ::: "memory");
        asm volatile("cp.async.bulk.wait_group 0;" ::: "memory");
    }
    __syncthreads();
}

extern "C" void kernel_launch(void* const* d_in, const int* in_sizes, int n_in,
                              void* d_out, int out_size) {
    const float* x   = (const float*)d_in[0];
    const float* g1  = (const float*)d_in[1];
    const float* raw = (const float*)d_in[2];
    const int* bidx  = (const int*)d_in[3];
    float* y = (float*)d_out;

    build_filter_kernel<<<1, 256>>>(g1, raw, bidx);
    spectral_kernel<<<NBLK, 64>>>(x, y);
}

// round 6
// speedup vs baseline: 1.0292x; 1.0292x over previous
#include <cuda_runtime.h>
#include <cstdint>

// ============================================================================
// y = ifft2(fft2(x) * sqrt_lambda), ortho. x: (16,768,64,64) f32.
// Pack 2 images as one complex field (filter real & symmetric => exact).
// One CTA (64 thr) per pair; each thread owns a full 64-pt line in registers.
// 64-pt FFT = in-register 8x8 four-step. Direct coalesced LDG/STG to gmem.
// ONE 16KB smem plane (rotation-swizzled, conflict-free) reused re-then-im
// for the two inter-dimension transposes => 13 CTAs/SM instead of 6.
// ============================================================================

#define NPIX 4096
#define NBLK 6144           // 12288 images / 2

__device__ float  g_perm[NPIX];   // filter, permuted: g_perm[r*64 + q] = f[r][swap(q)]
__device__ float2 g_tw[64];       // W64^{b*c} at [b*8+c]

__device__ __forceinline__ float2 cadd(float2 a, float2 b) { return make_float2(a.x + b.x, a.y + b.y); }
__device__ __forceinline__ float2 csub(float2 a, float2 b) { return make_float2(a.x - b.x, a.y - b.y); }
__device__ __forceinline__ float2 cmul(float2 a, float2 b) {
    return make_float2(fmaf(a.x, b.x, -a.y * b.y), fmaf(a.x, b.y, a.y * b.x));
}
__device__ __forceinline__ float2 cmulc(float2 a, float2 b) {  // a * conj(b)
    return make_float2(fmaf(a.x, b.x, a.y * b.y), fmaf(a.y, b.x, -a.x * b.y));
}

template <bool INV>
__device__ __forceinline__ float2 mul_i(float2 a) {
    return INV ? make_float2(-a.y, a.x) : make_float2(a.y, -a.x);
}

template <bool INV>
__device__ __forceinline__ void fft8(float2* a) {
    const float C = 0.70710678118654752440f;
    float2 e0 = a[0], e1 = a[2], e2 = a[4], e3 = a[6];
    float2 o0 = a[1], o1 = a[3], o2 = a[5], o3 = a[7];
    float2 t0 = cadd(e0, e2), t1 = csub(e0, e2);
    float2 t2 = cadd(e1, e3), t3 = mul_i<INV>(csub(e1, e3));
    float2 E0 = cadd(t0, t2), E2 = csub(t0, t2);
    float2 E1 = cadd(t1, t3), E3 = csub(t1, t3);
    t0 = cadd(o0, o2); t1 = csub(o0, o2);
    t2 = cadd(o1, o3); t3 = mul_i<INV>(csub(o1, o3));
    float2 O0 = cadd(t0, t2), O2 = csub(t0, t2);
    float2 O1 = cadd(t1, t3), O3 = csub(t1, t3);
    if (!INV) {
        O1 = make_float2(C * (O1.x + O1.y), C * (O1.y - O1.x));
        O2 = make_float2(O2.y, -O2.x);
        O3 = make_float2(C * (O3.y - O3.x), C * (-O3.x - O3.y));
    } else {
        O1 = make_float2(C * (O1.x - O1.y), C * (O1.x + O1.y));
        O2 = make_float2(-O2.y, O2.x);
        O3 = make_float2(C * (-O3.x - O3.y), C * (O3.x - O3.y));
    }
    a[0] = cadd(E0, O0); a[4] = csub(E0, O0);
    a[1] = cadd(E1, O1); a[5] = csub(E1, O1);
    a[2] = cadd(E2, O2); a[6] = csub(E2, O2);
    a[3] = cadd(E3, O3); a[7] = csub(E3, O3);
}

// 64-pt FFT, natural input. Output digit-swapped: freq (c+8d) at slot (8c+d).
template <bool INV>
__device__ __forceinline__ void fft64_nat(float2* v, const float2* Tw) {
    #pragma unroll
    for (int b = 0; b < 8; b++) {
        float2 a[8];
        #pragma unroll
        for (int j = 0; j < 8; j++) a[j] = v[b + 8 * j];
        fft8<INV>(a);
        #pragma unroll
        for (int j = 0; j < 8; j++) v[b + 8 * j] = a[j];
    }
    #pragma unroll
    for (int b = 1; b < 8; b++)
        #pragma unroll
        for (int c = 1; c < 8; c++) {
            float2 t = Tw[b * 8 + c];
            v[8 * c + b] = INV ? cmulc(v[8 * c + b], t) : cmul(v[8 * c + b], t);
        }
    #pragma unroll
    for (int c = 0; c < 8; c++) fft8<INV>(v + 8 * c);
}

// 64-pt FFT, digit-swapped input, natural output.
template <bool INV>
__device__ __forceinline__ void fft64_swapin(float2* v, const float2* Tw) {
    #pragma unroll
    for (int c = 0; c < 8; c++) fft8<INV>(v + 8 * c);
    #pragma unroll
    for (int c = 1; c < 8; c++)
        #pragma unroll
        for (int e = 1; e < 8; e++) {
            float2 t = Tw[c * 8 + e];
            v[8 * c + e] = INV ? cmulc(v[8 * c + e], t) : cmul(v[8 * c + e], t);
        }
    #pragma unroll
    for (int e = 0; e < 8; e++) {
        float2 a[8];
        #pragma unroll
        for (int cc = 0; cc < 8; cc++) a[cc] = v[8 * cc + e];
        fft8<INV>(a);
        #pragma unroll
        for (int f = 0; f < 8; f++) v[e + 8 * f] = a[f];
    }
}

// ============================================================================
// Filter + twiddle build (tiny, one block).
// ============================================================================
__global__ void build_filter_kernel(const float* __restrict__ g1p,
                                    const float* __restrict__ raw_deltas,
                                    const int* __restrict__ bin_idx) {
    __shared__ float gbin[16];
    __shared__ float red[256];
    int tid = threadIdx.x;

    if (tid < 64) {
        int b = tid >> 3, c = tid & 7;
        float sv, cv;
        sincospif(-(float)(b * c) * (1.0f / 32.0f), &sv, &cv);
        g_tw[tid] = make_float2(cv, sv);
    }
    if (tid == 0) {
        float acc = g1p[0];
        gbin[0] = acc;
        #pragma unroll
        for (int i = 0; i < 15; i++) {
            float v = raw_deltas[i];
            float sp = (v > 20.0f) ? v : log1pf(expf(v));
            acc += sp;
            gbin[i + 1] = acc;
        }
    }
    __syncthreads();

    float ell[16];
    float s = 0.0f;
    #pragma unroll
    for (int i = 0; i < 16; i++) {
        int p = tid + 256 * i;
        ell[i] = gbin[bin_idx[p]];
        s += ell[i];
    }
    red[tid] = s;
    __syncthreads();
    for (int off = 128; off > 0; off >>= 1) {
        if (tid < off) red[tid] += red[tid + off];
        __syncthreads();
    }
    float m1 = red[0] * (1.0f / 4096.0f);
    __syncthreads();

    float s2 = 0.0f;
    #pragma unroll
    for (int i = 0; i < 16; i++) {
        float e = ell[i] - m1;
        e = fminf(3.0f, fmaxf(-3.0f, e));
        ell[i] = e;
        s2 += e;
    }
    red[tid] = s2;
    __syncthreads();
    for (int off = 128; off > 0; off >>= 1) {
        if (tid < off) red[tid] += red[tid + off];
        __syncthreads();
    }
    float m2 = red[0] * (1.0f / 4096.0f);

    #pragma unroll
    for (int i = 0; i < 16; i++) {
        int p = tid + 256 * i;              // p = r*64 + j
        float val = expf(0.5f * (ell[i] - m2)) * (1.0f / 4096.0f);
        int j = p & 63;
        int q = ((j & 7) << 3) | (j >> 3);  // swap(j)
        g_perm[(p & ~63) | q] = val;
    }
}

// ============================================================================
// Main kernel: 64 threads per pair, 16KB scratch plane (rotation swizzle).
// Rotation addr(row, col) = row*64 + ((col+row)&63):
//   fixed-row warp access -> 32 distinct banks; fixed-col warp access
//   (row varies over lanes) -> also 32 distinct banks. Zero conflicts.
// ============================================================================
__global__ void __launch_bounds__(64)
spectral_kernel(const float* __restrict__ x, float* __restrict__ y) {
    __shared__ float  S[NPIX];     // 16KB single scratch plane
    __shared__ float2 Tw[64];

    const int c = threadIdx.x;
    const size_t base = (size_t)blockIdx.x * (2 * NPIX);
    const float* A = x + base;
    const float* B = A + NPIX;

    float2 v[64];

    // Load column c of both images (coalesced).
    #pragma unroll
    for (int i = 0; i < 64; i++) {
        v[i].x = A[i * 64 + c];
        v[i].y = B[i * 64 + c];
    }
    Tw[c] = g_tw[c];
    __syncthreads();

    // Forward column FFT (output slot q holds freq swap(q)).
    fft64_nat<false>(v, Tw);

    // ---- Transpose 1: re pass then im pass through the single plane.
    const int r = c;  // row owned in row-phase
    #pragma unroll
    for (int m = 0; m < 64; m++) {
        int s = ((m & 7) << 3) | (m >> 3);         // slot holding freq m
        S[m * 64 + ((c + m) & 63)] = v[s].x;
    }
    __syncthreads();
    #pragma unroll
    for (int j = 0; j < 64; j++)
        v[j].x = S[r * 64 + ((j + r) & 63)];       // new row data (re)
    __syncthreads();
    #pragma unroll
    for (int m = 0; m < 64; m++) {
        int s = ((m & 7) << 3) | (m >> 3);
        S[m * 64 + ((c + m) & 63)] = v[s].y;       // old column data (im)
    }
    __syncthreads();
    #pragma unroll
    for (int j = 0; j < 64; j++)
        v[j].y = S[r * 64 + ((j + r) & 63)];
    __syncthreads();

    // ---- Row phase: fwd row FFT + filter + inv row FFT (all registers).
    fft64_nat<false>(v, Tw);
    {
        const float4* F = (const float4*)g_perm;
        #pragma unroll
        for (int k = 0; k < 16; k++) {
            float4 f = __ldg(&F[r * 16 + k]);
            v[4 * k + 0].x *= f.x; v[4 * k + 0].y *= f.x;
            v[4 * k + 1].x *= f.y; v[4 * k + 1].y *= f.y;
            v[4 * k + 2].x *= f.z; v[4 * k + 2].y *= f.z;
            v[4 * k + 3].x *= f.w; v[4 * k + 3].y *= f.w;
        }
    }
    fft64_swapin<true>(v, Tw);   // natural j-order output

    // ---- Transpose 2: re pass then im pass.
    #pragma unroll
    for (int j = 0; j < 64; j++)
        S[r * 64 + ((j + r) & 63)] = v[j].x;
    __syncthreads();
    #pragma unroll
    for (int m = 0; m < 64; m++)
        v[m].x = S[m * 64 + ((c + m) & 63)];       // column data (re)
    __syncthreads();
    #pragma unroll
    for (int j = 0; j < 64; j++)
        S[r * 64 + ((j + r) & 63)] = v[j].y;
    __syncthreads();
    #pragma unroll
    for (int m = 0; m < 64; m++)
        v[m].y = S[m * 64 + ((c + m) & 63)];

    // Inverse column FFT (natural freq-row in, swapped spatial out).
    fft64_nat<true>(v, Tw);

    float* Ya = y + base;
    float* Yb = Ya + NPIX;
    #pragma unroll
    for (int i = 0; i < 64; i++) {
        int s = ((i & 7) << 3) | (i >> 3);         // slot holding spatial row i
        Ya[i * 64 + c] = v[s].x;
        Yb[i * 64 + c] = v[s].y;
    }
}

extern "C" void kernel_launch(void* const* d_in, const int* in_sizes, int n_in,
                              void* d_out, int out_size) {
    const float* x   = (const float*)d_in[0];
    const float* g1  = (const float*)d_in[1];
    const float* raw = (const float*)d_in[2];
    const int* bidx  = (const int*)d_in[3];
    float* y = (float*)d_out;

    build_filter_kernel<<<1, 256>>>(g1, raw, bidx);
    spectral_kernel<<<NBLK, 64>>>(x, y);
}

// round 7
// speedup vs baseline: 1.1650x; 1.1320x over previous
#include <cuda_runtime.h>
#include <cstdint>

// ============================================================================
// y = ifft2(fft2(x) * sqrt_lambda), ortho. x: (16,768,64,64) f32.
// Pack 2 images as one complex field (filter real & symmetric => exact).
// One CTA (64 thr) per pair; each thread owns a full 64-pt line in registers.
// Complex numbers held as PACKED f32x2 (64-bit reg pairs); butterflies use
// Blackwell add/sub/fma.rn.f32x2 (halves FMA-pipe ops). Twiddles are
// compile-time immediates (FFMA-imm, rt 1). One 16KB rotation-swizzled smem
// plane for the two inter-dimension transposes.
// ============================================================================

#define NPIX 4096
#define NBLK 6144           // 12288 images / 2

typedef unsigned long long u64c;

__device__ float g_perm[NPIX];   // filter, permuted: g_perm[r*64 + q] = f[r][swap(q)]

// ---- packed f32x2 primitives -----------------------------------------------
__device__ __forceinline__ u64c PADD(u64c a, u64c b) {
    u64c d; asm("add.rn.f32x2 %0,%1,%2;" : "=l"(d) : "l"(a), "l"(b)); return d;
}
__device__ __forceinline__ u64c PSUB(u64c a, u64c b) {
    u64c d; asm("sub.rn.f32x2 %0,%1,%2;" : "=l"(d) : "l"(a), "l"(b)); return d;
}
__device__ __forceinline__ u64c PMUL(u64c a, u64c b) {
    u64c d; asm("mul.rn.f32x2 %0,%1,%2;" : "=l"(d) : "l"(a), "l"(b)); return d;
}
__device__ __forceinline__ u64c PFMA(u64c a, u64c b, u64c c) {
    u64c d; asm("fma.rn.f32x2 %0,%1,%2,%3;" : "=l"(d) : "l"(a), "l"(b), "l"(c)); return d;
}
__device__ __forceinline__ float PLO(u64c v) { return __uint_as_float((unsigned)v); }
__device__ __forceinline__ float PHI(u64c v) { return __uint_as_float((unsigned)(v >> 32)); }
__device__ __forceinline__ u64c PPK(float x, float y) {
    return ((u64c)__float_as_uint(y) << 32) | (u64c)__float_as_uint(x);
}
__device__ __forceinline__ u64c PSWAP(u64c v) { return (v >> 32) | (v << 32); }

// packed sign constants (bit patterns; 1.0=0x3F800000, C=0.70710678f=0x3F3504F3)
#define P1M1  0xBF8000003F800000ULL   // ( 1, -1)
#define M1P1  0x3F800000BF800000ULL   // (-1,  1)
#define CCp   0x3F3504F33F3504F3ULL   // ( C,  C)
#define CMCp  0xBF3504F33F3504F3ULL   // ( C, -C)
#define MCCp  0x3F3504F3BF3504F3ULL   // (-C,  C)
#define MCMCp 0xBF3504F3BF3504F3ULL   // (-C, -C)

// ---- compile-time twiddle tables: cos/sin(pi*k/32), k = 0..49 --------------
__device__ constexpr float COS_T[50] = {
    1.000000000f, 0.995184727f, 0.980785280f, 0.956940336f, 0.923879533f,
    0.881921264f, 0.831469612f, 0.773010453f, 0.707106781f, 0.634393284f,
    0.555570233f, 0.471396737f, 0.382683432f, 0.290284677f, 0.195090322f,
    0.098017140f, 0.000000000f,-0.098017140f,-0.195090322f,-0.290284677f,
   -0.382683432f,-0.471396737f,-0.555570233f,-0.634393284f,-0.707106781f,
   -0.773010453f,-0.831469612f,-0.881921264f,-0.923879533f,-0.956940336f,
   -0.980785280f,-0.995184727f,-1.000000000f,-0.995184727f,-0.980785280f,
   -0.956940336f,-0.923879533f,-0.881921264f,-0.831469612f,-0.773010453f,
   -0.707106781f,-0.634393284f,-0.555570233f,-0.471396737f,-0.382683432f,
   -0.290284677f,-0.195090322f,-0.098017140f, 0.000000000f, 0.098017140f };
__device__ constexpr float SIN_T[50] = {
    0.000000000f, 0.098017140f, 0.195090322f, 0.290284677f, 0.382683432f,
    0.471396737f, 0.555570233f, 0.634393284f, 0.707106781f, 0.773010453f,
    0.831469612f, 0.881921264f, 0.923879533f, 0.956940336f, 0.980785280f,
    0.995184727f, 1.000000000f, 0.995184727f, 0.980785280f, 0.956940336f,
    0.923879533f, 0.881921264f, 0.831469612f, 0.773010453f, 0.707106781f,
    0.634393284f, 0.555570233f, 0.471396737f, 0.382683432f, 0.290284677f,
    0.195090322f, 0.098017140f, 0.000000000f,-0.098017140f,-0.195090322f,
   -0.290284677f,-0.382683432f,-0.471396737f,-0.555570233f,-0.634393284f,
   -0.707106781f,-0.773010453f,-0.831469612f,-0.881921264f,-0.923879533f,
   -0.956940336f,-0.980785280f,-0.995184727f,-1.000000000f,-0.995184727f };

// multiply by W64^k (fwd: e^{-i pi k/32}; INV: conjugate). k compile-time.
template <bool INV>
__device__ __forceinline__ u64c ctw(u64c v, int k) {
    const float wx = COS_T[k];
    const float wy = INV ? SIN_T[k] : -SIN_T[k];
    float x = PLO(v), y = PHI(v);
    float rx = fmaf(x, wx, -(y * wy));
    float ry = fmaf(x, wy, y * wx);
    return PPK(rx, ry);
}

// ---- packed radix-8 butterfly (natural order in/out) -----------------------
template <bool INV>
__device__ __forceinline__ void fft8p(u64c* a) {
    const u64c Ka = INV ? M1P1 : P1M1;   // "+i" fma const
    const u64c Kb = INV ? P1M1 : M1P1;   // "-i" fma const
    const u64c Kt = INV ? MCCp : CMCp;   // W8 twiddle helper const
    u64c e0 = a[0], o0 = a[1], e1 = a[2], o1 = a[3];
    u64c e2 = a[4], o2 = a[5], e3 = a[6], o3 = a[7];
    // FFT4 on evens
    u64c t0 = PADD(e0, e2), t1 = PSUB(e0, e2);
    u64c t2 = PADD(e1, e3), u  = PSUB(e1, e3);
    u64c su = PSWAP(u);
    u64c E0 = PADD(t0, t2), E2 = PSUB(t0, t2);
    u64c E1 = PFMA(su, Ka, t1), E3 = PFMA(su, Kb, t1);
    // FFT4 on odds
    u64c p0 = PADD(o0, o2), p1 = PSUB(o0, o2);
    u64c p2 = PADD(o1, o3), q  = PSUB(o1, o3);
    u64c sq = PSWAP(q);
    u64c O0 = PADD(p0, p2), O2 = PSUB(p0, p2);
    u64c O1 = PFMA(sq, Ka, p1), O3 = PFMA(sq, Kb, p1);
    // twiddle odds: O1 *= W8^{+-1}, O3 *= W8^{+-3}; O2 (*= +-i) folded below
    u64c s1 = PSWAP(O1);
    O1 = PFMA(O1, CCp,   PMUL(s1, Kt));
    u64c s3 = PSWAP(O3);
    O3 = PFMA(O3, MCMCp, PMUL(s3, Kt));
    u64c s2 = PSWAP(O2);
    a[0] = PADD(E0, O0); a[4] = PSUB(E0, O0);
    a[1] = PADD(E1, O1); a[5] = PSUB(E1, O1);
    a[2] = PFMA(s2, Ka, E2); a[6] = PFMA(s2, Kb, E2);
    a[3] = PADD(E3, O3); a[7] = PSUB(E3, O3);
}

// 64-pt FFT, natural input. Output digit-swapped: freq (c+8d) at slot (8c+d).
template <bool INV>
__device__ __forceinline__ void fft64_nat(u64c* v) {
    #pragma unroll
    for (int b = 0; b < 8; b++) {
        u64c a[8];
        #pragma unroll
        for (int j = 0; j < 8; j++) a[j] = v[b + 8 * j];
        fft8p<INV>(a);
        #pragma unroll
        for (int j = 0; j < 8; j++) v[b + 8 * j] = a[j];
    }
    #pragma unroll
    for (int b = 1; b < 8; b++)
        #pragma unroll
        for (int c = 1; c < 8; c++)
            v[8 * c + b] = ctw<INV>(v[8 * c + b], b * c);
    #pragma unroll
    for (int c = 0; c < 8; c++) fft8p<INV>(v + 8 * c);
}

// 64-pt FFT, digit-swapped input, natural output.
template <bool INV>
__device__ __forceinline__ void fft64_swapin(u64c* v) {
    #pragma unroll
    for (int c = 0; c < 8; c++) fft8p<INV>(v + 8 * c);
    #pragma unroll
    for (int c = 1; c < 8; c++)
        #pragma unroll
        for (int e = 1; e < 8; e++)
            v[8 * c + e] = ctw<INV>(v[8 * c + e], c * e);
    #pragma unroll
    for (int e = 0; e < 8; e++) {
        u64c a[8];
        #pragma unroll
        for (int cc = 0; cc < 8; cc++) a[cc] = v[8 * cc + e];
        fft8p<INV>(a);
        #pragma unroll
        for (int f = 0; f < 8; f++) v[e + 8 * f] = a[f];
    }
}

// ============================================================================
// Filter build (tiny, one block).
// ============================================================================
__global__ void build_filter_kernel(const float* __restrict__ g1p,
                                    const float* __restrict__ raw_deltas,
                                    const int* __restrict__ bin_idx) {
    __shared__ float gbin[16];
    __shared__ float red[256];
    int tid = threadIdx.x;

    if (tid == 0) {
        float acc = g1p[0];
        gbin[0] = acc;
        #pragma unroll
        for (int i = 0; i < 15; i++) {
            float v = raw_deltas[i];
            float sp = (v > 20.0f) ? v : log1pf(expf(v));
            acc += sp;
            gbin[i + 1] = acc;
        }
    }
    __syncthreads();

    float ell[16];
    float s = 0.0f;
    #pragma unroll
    for (int i = 0; i < 16; i++) {
        int p = tid + 256 * i;
        ell[i] = gbin[bin_idx[p]];
        s += ell[i];
    }
    red[tid] = s;
    __syncthreads();
    for (int off = 128; off > 0; off >>= 1) {
        if (tid < off) red[tid] += red[tid + off];
        __syncthreads();
    }
    float m1 = red[0] * (1.0f / 4096.0f);
    __syncthreads();

    float s2 = 0.0f;
    #pragma unroll
    for (int i = 0; i < 16; i++) {
        float e = ell[i] - m1;
        e = fminf(3.0f, fmaxf(-3.0f, e));
        ell[i] = e;
        s2 += e;
    }
    red[tid] = s2;
    __syncthreads();
    for (int off = 128; off > 0; off >>= 1) {
        if (tid < off) red[tid] += red[tid + off];
        __syncthreads();
    }
    float m2 = red[0] * (1.0f / 4096.0f);

    #pragma unroll
    for (int i = 0; i < 16; i++) {
        int p = tid + 256 * i;              // p = r*64 + j
        float val = expf(0.5f * (ell[i] - m2)) * (1.0f / 4096.0f);
        int j = p & 63;
        int q = ((j & 7) << 3) | (j >> 3);  // swap(j)
        g_perm[(p & ~63) | q] = val;
    }
}

// ============================================================================
// Main kernel: 64 threads per pair, 16KB rotation-swizzled scratch plane.
// ============================================================================
__global__ void __launch_bounds__(64, 6)
spectral_kernel(const float* __restrict__ x, float* __restrict__ y) {
    __shared__ float S[NPIX];     // 16KB single scratch plane

    const int c = threadIdx.x;
    const size_t base = (size_t)blockIdx.x * (2 * NPIX);
    const float* A = x + base;
    const float* B = A + NPIX;

    u64c v[64];

    // Load column c of both images (coalesced).
    #pragma unroll
    for (int i = 0; i < 64; i++)
        v[i] = PPK(A[i * 64 + c], B[i * 64 + c]);

    // Forward column FFT (output slot q holds freq swap(q)).
    fft64_nat<false>(v);

    // ---- Transpose 1: re pass then im pass through the single plane.
    const int r = c;  // row owned in row-phase
    #pragma unroll
    for (int m = 0; m < 64; m++) {
        int s = ((m & 7) << 3) | (m >> 3);         // slot holding freq m
        S[m * 64 + ((c + m) & 63)] = PLO(v[s]);
    }
    __syncthreads();
    float nx[64];
    #pragma unroll
    for (int j = 0; j < 64; j++)
        nx[j] = S[r * 64 + ((j + r) & 63)];        // new row data (re)
    __syncthreads();
    #pragma unroll
    for (int m = 0; m < 64; m++) {
        int s = ((m & 7) << 3) | (m >> 3);
        S[m * 64 + ((c + m) & 63)] = PHI(v[s]);    // old column data (im)
    }
    __syncthreads();
    #pragma unroll
    for (int j = 0; j < 64; j++)
        v[j] = PPK(nx[j], S[r * 64 + ((j + r) & 63)]);
    __syncthreads();

    // ---- Row phase: fwd row FFT + filter + inv row FFT (all registers).
    fft64_nat<false>(v);
    {
        const float4* F = (const float4*)g_perm;
        #pragma unroll
        for (int k = 0; k < 16; k++) {
            float4 f = __ldg(&F[r * 16 + k]);
            v[4 * k + 0] = PMUL(v[4 * k + 0], PPK(f.x, f.x));
            v[4 * k + 1] = PMUL(v[4 * k + 1], PPK(f.y, f.y));
            v[4 * k + 2] = PMUL(v[4 * k + 2], PPK(f.z, f.z));
            v[4 * k + 3] = PMUL(v[4 * k + 3], PPK(f.w, f.w));
        }
    }
    fft64_swapin<true>(v);   // natural j-order output

    // ---- Transpose 2: re pass then im pass.
    #pragma unroll
    for (int j = 0; j < 64; j++)
        S[r * 64 + ((j + r) & 63)] = PLO(v[j]);
    __syncthreads();
    #pragma unroll
    for (int m = 0; m < 64; m++)
        nx[m] = S[m * 64 + ((c + m) & 63)];        // column data (re)
    __syncthreads();
    #pragma unroll
    for (int j = 0; j < 64; j++)
        S[r * 64 + ((j + r) & 63)] = PHI(v[j]);
    __syncthreads();
    #pragma unroll
    for (int m = 0; m < 64; m++)
        v[m] = PPK(nx[m], S[m * 64 + ((c + m) & 63)]);

    // Inverse column FFT (natural freq-row in, swapped spatial out).
    fft64_nat<true>(v);

    float* Ya = y + base;
    float* Yb = Ya + NPIX;
    #pragma unroll
    for (int i = 0; i < 64; i++) {
        int s = ((i & 7) << 3) | (i >> 3);         // slot holding spatial row i
        Ya[i * 64 + c] = PLO(v[s]);
        Yb[i * 64 + c] = PHI(v[s]);
    }
}

extern "C" void kernel_launch(void* const* d_in, const int* in_sizes, int n_in,
                              void* d_out, int out_size) {
    const float* x   = (const float*)d_in[0];
    const float* g1  = (const float*)d_in[1];
    const float* raw = (const float*)d_in[2];
    const int* bidx  = (const int*)d_in[3];
    float* y = (float*)d_out;

    build_filter_kernel<<<1, 256>>>(g1, raw, bidx);
    spectral_kernel<<<NBLK, 64>>>(x, y);
}